// round 3
// baseline (speedup 1.0000x reference)
#include <cuda_runtime.h>
#include <cuda_bf16.h>
#include <math.h>
#include <stdint.h>

// Problem dims
#define B_  32
#define S_  128
#define T_  64
#define E_  64
#define H_  512
#define V_  32000
#define G3  1536            // 3*H
#define TD  63              // decoder steps (T-1)
#define M_FC (TD*B_)        // 2016 rows for final GEMM

#define NBLK  296           // persistent grid (<= 2 per SM on 148/152-SM parts)
#define NTHR  256
#define NWARP (NBLK*(NTHR/32))

// ---------------- scratch (device globals; no allocation allowed) -------------
__device__ float g_srcET [S_*E_*B_];          // [s][k][b]
__device__ float g_trgET [TD*E_*B_];          // [t][k][b]
__device__ float g_encGI [S_*G3*B_];          // [s][jg][b]
__device__ float g_giEmb [TD*G3*B_];          // [t][jg][b]
__device__ float g_encOut[S_*H_*B_];          // [s][j][b]
__device__ float g_encProj[S_*H_*B_];         // [s][j][b]
__device__ float g_hproj [H_*B_];
__device__ float g_spart [S_*4*B_];           // scores partials [s][c][b]
__device__ float g_wts   [S_*B_];             // softmax weights [s][b]
__device__ float g_ctx   [H_*B_];
__device__ float g_h0A[H_*B_], g_h0B[H_*B_];
__device__ float g_h1A[H_*B_], g_h1B[H_*B_];
__device__ float g_h1rm [M_FC*H_];            // row-major A for final GEMM

// ---------------- software grid barrier ---------------------------------------
__device__ unsigned int g_bar_count = 0;
__device__ volatile unsigned int g_bar_gen = 0;

__device__ __forceinline__ void grid_barrier() {
    __syncthreads();
    if (threadIdx.x == 0) {
        __threadfence();
        unsigned int gen = g_bar_gen;
        if (atomicInc(&g_bar_count, NBLK - 1) == NBLK - 1) {
            g_bar_gen = gen + 1;              // release
        } else {
            while (g_bar_gen == gen) { __nanosleep(32); }
        }
        __threadfence();
    }
    __syncthreads();
}

__device__ __forceinline__ float sigf(float x) { return 1.0f / (1.0f + expf(-x)); }

// =============================================================================
// Kernel 1: embeddings, input-side GEMMs, encoder scan, attention precompute
// =============================================================================
__global__ void __launch_bounds__(NTHR, 2)
k_encoder(const int* __restrict__ src, const int* __restrict__ trg,
          const float* __restrict__ src_embed, const float* __restrict__ trg_embed,
          const float* __restrict__ eWih, const float* __restrict__ eWhh,
          const float* __restrict__ eBih, const float* __restrict__ eBhh,
          const float* __restrict__ d0Wih, const float* __restrict__ d0Bih,
          const float* __restrict__ attnW, const float* __restrict__ attnB)
{
    const int lane = threadIdx.x & 31;
    const int gw   = blockIdx.x * (NTHR/32) + (threadIdx.x >> 5);
    const int gtid = blockIdx.x * NTHR + threadIdx.x;
    const int NT   = NBLK * NTHR;

    // ---- P0: gather embeddings into transposed [.,k,b] layout ----
    for (int i = gtid; i < S_*E_*B_; i += NT) {
        int b = i & 31, k = (i >> 5) & 63, s = i >> 11;
        g_srcET[i] = src_embed[(size_t)src[b*S_ + s]*E_ + k];
    }
    for (int i = gtid; i < TD*E_*B_; i += NT) {
        int b = i & 31, k = (i >> 5) & 63, t = i >> 11;
        g_trgET[i] = trg_embed[(size_t)trg[b*T_ + t]*E_ + k];
    }
    grid_barrier();

    // ---- P1: encoder gi for all steps + decoder embedding-half gi ----
    for (int id = gw; id < S_*G3; id += NWARP) {
        int s = id / G3, jg = id - s*G3;
        float acc = eBih[jg];
        const float* w  = eWih + (size_t)jg*E_;
        const float* xe = g_srcET + (size_t)s*E_*B_ + lane;
        #pragma unroll 8
        for (int k = 0; k < E_; k++) acc = fmaf(w[k], xe[k*B_], acc);
        g_encGI[(size_t)id*B_ + lane] = acc;
    }
    for (int id = gw; id < TD*G3; id += NWARP) {
        int t = id / G3, jg = id - t*G3;
        float acc = d0Bih[jg];
        const float* w  = d0Wih + (size_t)jg*(E_+H_);   // first 64 cols = embedding part
        const float* xe = g_trgET + (size_t)t*E_*B_ + lane;
        #pragma unroll 8
        for (int k = 0; k < E_; k++) acc = fmaf(w[k], xe[k*B_], acc);
        g_giEmb[(size_t)id*B_ + lane] = acc;
    }
    grid_barrier();

    // ---- P2: encoder recurrent scan ----
    for (int t = 0; t < S_; t++) {
        for (int j = gw; j < H_; j += NWARP) {
            const float* gi = g_encGI + (size_t)t*G3*B_ + lane;
            float gir = gi[(size_t)j*B_];
            float giz = gi[(size_t)(H_ + j)*B_];
            float gin = gi[(size_t)(2*H_ + j)*B_];
            float ghr = eBhh[j], ghz = eBhh[H_ + j], ghn = eBhh[2*H_ + j];
            float hj = 0.0f;
            if (t > 0) {
                const float* hp = g_encOut + (size_t)(t-1)*H_*B_ + lane;
                const float* w0 = eWhh + (size_t)j*H_;
                const float* w1 = eWhh + (size_t)(H_ + j)*H_;
                const float* w2 = eWhh + (size_t)(2*H_ + j)*H_;
                #pragma unroll 4
                for (int k = 0; k < H_; k++) {
                    float h = hp[(size_t)k*B_];
                    ghr = fmaf(w0[k], h, ghr);
                    ghz = fmaf(w1[k], h, ghz);
                    ghn = fmaf(w2[k], h, ghn);
                }
                hj = hp[(size_t)j*B_];
            }
            float r = sigf(gir + ghr);
            float z = sigf(giz + ghz);
            float n = tanhf(gin + r*ghn);
            g_encOut[((size_t)t*H_ + j)*B_ + lane] = (1.0f - z)*n + z*hj;
        }
        grid_barrier();
    }

    // ---- P3: enc_proj = enc_outs @ attn_W[:,H:2H]^T + attn_b ----
    for (int id = gw; id < S_*H_; id += NWARP) {
        int s = id >> 9, j = id & (H_-1);
        float acc = attnB[j];
        const float* w  = attnW + (size_t)j*(2*H_) + H_;
        const float* eo = g_encOut + (size_t)s*H_*B_ + lane;
        #pragma unroll 4
        for (int k = 0; k < H_; k++) acc = fmaf(w[k], eo[(size_t)k*B_], acc);
        g_encProj[(size_t)id*B_ + lane] = acc;
    }
}

// =============================================================================
// Kernel 2: decoder scan (attention + 2 GRU layers per step)
// =============================================================================
__global__ void __launch_bounds__(NTHR, 2)
k_decoder(const float* __restrict__ attnW, const float* __restrict__ vW,
          const float* __restrict__ d0Wih, const float* __restrict__ d0Whh,
          const float* __restrict__ d0Bhh,
          const float* __restrict__ d1Wih, const float* __restrict__ d1Whh,
          const float* __restrict__ d1Bih, const float* __restrict__ d1Bhh)
{
    const int lane = threadIdx.x & 31;
    const int gw   = blockIdx.x * (NTHR/32) + (threadIdx.x >> 5);
    const float* encLast = g_encOut + (size_t)(S_-1)*H_*B_;

    for (int t = 0; t < TD; t++) {
        const float* h0in = (t == 0) ? encLast : ((t & 1) ? g_h0B : g_h0A);
        const float* h1in = (t == 0) ? encLast : ((t & 1) ? g_h1B : g_h1A);
        float* h0out = (t & 1) ? g_h0A : g_h0B;
        float* h1out = (t & 1) ? g_h1A : g_h1B;

        // phase a: hproj = h1 @ attn_W[:,0:H]^T
        for (int j = gw; j < H_; j += NWARP) {
            float acc = 0.0f;
            const float* w = attnW + (size_t)j*(2*H_);
            #pragma unroll 4
            for (int k = 0; k < H_; k++) acc = fmaf(w[k], h1in[(size_t)k*B_ + lane], acc);
            g_hproj[(size_t)j*B_ + lane] = acc;
        }
        grid_barrier();

        // phase b: score partials   score[b,s] = sum_j v[j]*tanh(hproj + encProj)
        for (int id = gw; id < S_*4; id += NWARP) {
            int s = id >> 2, c = id & 3;
            float acc = 0.0f;
            const float* ep = g_encProj + (size_t)s*H_*B_ + lane;
            int k0 = c * (H_/4);
            #pragma unroll 4
            for (int k = k0; k < k0 + H_/4; k++) {
                float e = tanhf(g_hproj[(size_t)k*B_ + lane] + ep[(size_t)k*B_]);
                acc = fmaf(vW[k], e, acc);
            }
            g_spart[(size_t)id*B_ + lane] = acc;
        }
        grid_barrier();

        // phase c: softmax over s (one warp per batch, lanes over s)
        if (gw < B_) {
            int b = gw;
            float sc[4];
            #pragma unroll
            for (int q = 0; q < 4; q++) {
                int s = lane + q*32;
                const float* p = g_spart + (size_t)(s*4)*B_ + b;
                sc[q] = p[0] + p[B_] + p[2*B_] + p[3*B_];
            }
            float m = fmaxf(fmaxf(sc[0], sc[1]), fmaxf(sc[2], sc[3]));
            #pragma unroll
            for (int o = 16; o > 0; o >>= 1) m = fmaxf(m, __shfl_xor_sync(0xffffffffu, m, o));
            float e[4], lsum = 0.0f;
            #pragma unroll
            for (int q = 0; q < 4; q++) { e[q] = expf(sc[q] - m); lsum += e[q]; }
            #pragma unroll
            for (int o = 16; o > 0; o >>= 1) lsum += __shfl_xor_sync(0xffffffffu, lsum, o);
            float inv = 1.0f / lsum;
            #pragma unroll
            for (int q = 0; q < 4; q++) g_wts[(size_t)(lane + q*32)*B_ + b] = e[q] * inv;
        }
        grid_barrier();

        // phase d: context = sum_s w[s]*enc_outs[s]
        for (int j = gw; j < H_; j += NWARP) {
            float acc = 0.0f;
            const float* eo = g_encOut + (size_t)j*B_ + lane;
            #pragma unroll 4
            for (int s = 0; s < S_; s++)
                acc = fmaf(g_wts[(size_t)s*B_ + lane], eo[(size_t)s*H_*B_], acc);
            g_ctx[(size_t)j*B_ + lane] = acc;
        }
        grid_barrier();

        // phase e: decoder GRU layer 0  (input = [emb ; context])
        for (int j = gw; j < H_; j += NWARP) {
            const float* gie = g_giEmb + (size_t)t*G3*B_ + lane;
            float gir = gie[(size_t)j*B_];
            float giz = gie[(size_t)(H_ + j)*B_];
            float gin = gie[(size_t)(2*H_ + j)*B_];
            float ghr = d0Bhh[j], ghz = d0Bhh[H_ + j], ghn = d0Bhh[2*H_ + j];
            const float* wi0 = d0Wih + (size_t)j*(E_+H_) + E_;
            const float* wi1 = d0Wih + (size_t)(H_ + j)*(E_+H_) + E_;
            const float* wi2 = d0Wih + (size_t)(2*H_ + j)*(E_+H_) + E_;
            const float* wh0 = d0Whh + (size_t)j*H_;
            const float* wh1 = d0Whh + (size_t)(H_ + j)*H_;
            const float* wh2 = d0Whh + (size_t)(2*H_ + j)*H_;
            #pragma unroll 2
            for (int k = 0; k < H_; k++) {
                float cv = g_ctx[(size_t)k*B_ + lane];
                float hv = h0in[(size_t)k*B_ + lane];
                gir = fmaf(wi0[k], cv, gir);
                giz = fmaf(wi1[k], cv, giz);
                gin = fmaf(wi2[k], cv, gin);
                ghr = fmaf(wh0[k], hv, ghr);
                ghz = fmaf(wh1[k], hv, ghz);
                ghn = fmaf(wh2[k], hv, ghn);
            }
            float r = sigf(gir + ghr);
            float z = sigf(giz + ghz);
            float n = tanhf(gin + r*ghn);
            h0out[(size_t)j*B_ + lane] = (1.0f - z)*n + z*h0in[(size_t)j*B_ + lane];
        }
        grid_barrier();

        // phase f: decoder GRU layer 1 (input = h0out)
        for (int j = gw; j < H_; j += NWARP) {
            float gir = d1Bih[j], giz = d1Bih[H_ + j], gin = d1Bih[2*H_ + j];
            float ghr = d1Bhh[j], ghz = d1Bhh[H_ + j], ghn = d1Bhh[2*H_ + j];
            const float* wi0 = d1Wih + (size_t)j*H_;
            const float* wi1 = d1Wih + (size_t)(H_ + j)*H_;
            const float* wi2 = d1Wih + (size_t)(2*H_ + j)*H_;
            const float* wh0 = d1Whh + (size_t)j*H_;
            const float* wh1 = d1Whh + (size_t)(H_ + j)*H_;
            const float* wh2 = d1Whh + (size_t)(2*H_ + j)*H_;
            #pragma unroll 2
            for (int k = 0; k < H_; k++) {
                float xv = h0out[(size_t)k*B_ + lane];
                float hv = h1in [(size_t)k*B_ + lane];
                gir = fmaf(wi0[k], xv, gir);
                giz = fmaf(wi1[k], xv, giz);
                gin = fmaf(wi2[k], xv, gin);
                ghr = fmaf(wh0[k], hv, ghr);
                ghz = fmaf(wh1[k], hv, ghz);
                ghn = fmaf(wh2[k], hv, ghn);
            }
            float r = sigf(gir + ghr);
            float z = sigf(giz + ghz);
            float n = tanhf(gin + r*ghn);
            float h1v = (1.0f - z)*n + z*h1in[(size_t)j*B_ + lane];
            h1out[(size_t)j*B_ + lane] = h1v;
            g_h1rm[(size_t)(t*B_ + lane)*H_ + j] = h1v;     // row-major for fc GEMM
        }
        grid_barrier();
    }
}

// =============================================================================
// Kernel 3: zero the t=0 output slice
// =============================================================================
__global__ void k_zero(float* __restrict__ out) {
    int i = blockIdx.x * blockDim.x + threadIdx.x;
    if (i < B_*V_) {
        int b = i / V_, v = i - b*V_;
        out[(size_t)b*T_*V_ + v] = 0.0f;
    }
}

// =============================================================================
// Kernel 4: final projection  C[2016,32000] = h1_all @ fc_W^T + fc_b
//           scattered into out[b, t+1, :]
// =============================================================================
__global__ void __launch_bounds__(256)
k_fc(const float* __restrict__ W, const float* __restrict__ bias,
     float* __restrict__ out)
{
    __shared__ float As[16][128];
    __shared__ float Bs[16][128];
    const int tid  = threadIdx.x;
    const int row0 = blockIdx.y * 128;
    const int col0 = blockIdx.x * 128;

    const int warp = tid >> 5, lane = tid & 31;
    const int m0 = (warp & 3) * 32 + (lane & 3) * 8;
    const int n0 = (warp >> 2) * 64 + (lane >> 2) * 8;

    float acc[8][8];
    #pragma unroll
    for (int i = 0; i < 8; i++)
        #pragma unroll
        for (int j = 0; j < 8; j++) acc[i][j] = 0.0f;

    const int lr = tid >> 2;           // 0..63
    const int lk = (tid & 3) * 4;      // 0,4,8,12

    for (int k0 = 0; k0 < H_; k0 += 16) {
        #pragma unroll
        for (int h = 0; h < 2; h++) {
            int r = row0 + lr + h*64;
            float4 v = make_float4(0.f, 0.f, 0.f, 0.f);
            if (r < M_FC)
                v = *reinterpret_cast<const float4*>(g_h1rm + (size_t)r*H_ + k0 + lk);
            As[lk+0][lr + h*64] = v.x;
            As[lk+1][lr + h*64] = v.y;
            As[lk+2][lr + h*64] = v.z;
            As[lk+3][lr + h*64] = v.w;
        }
        #pragma unroll
        for (int h = 0; h < 2; h++) {
            int c = col0 + lr + h*64;
            float4 v = *reinterpret_cast<const float4*>(W + (size_t)c*H_ + k0 + lk);
            Bs[lk+0][lr + h*64] = v.x;
            Bs[lk+1][lr + h*64] = v.y;
            Bs[lk+2][lr + h*64] = v.z;
            Bs[lk+3][lr + h*64] = v.w;
        }
        __syncthreads();
        #pragma unroll
        for (int kk = 0; kk < 16; kk++) {
            float4 a0 = *reinterpret_cast<const float4*>(&As[kk][m0]);
            float4 a1 = *reinterpret_cast<const float4*>(&As[kk][m0+4]);
            float4 b0 = *reinterpret_cast<const float4*>(&Bs[kk][n0]);
            float4 b1 = *reinterpret_cast<const float4*>(&Bs[kk][n0+4]);
            float av[8] = {a0.x,a0.y,a0.z,a0.w,a1.x,a1.y,a1.z,a1.w};
            float bv[8] = {b0.x,b0.y,b0.z,b0.w,b1.x,b1.y,b1.z,b1.w};
            #pragma unroll
            for (int i = 0; i < 8; i++)
                #pragma unroll
                for (int j = 0; j < 8; j++)
                    acc[i][j] = fmaf(av[i], bv[j], acc[i][j]);
        }
        __syncthreads();
    }

    #pragma unroll
    for (int i = 0; i < 8; i++) {
        int r = row0 + m0 + i;
        if (r >= M_FC) continue;
        int b = r & 31, t = r >> 5;
        float* o = out + (size_t)b*T_*V_ + (size_t)(t+1)*V_ + col0 + n0;
        #pragma unroll
        for (int j = 0; j < 8; j += 4) {
            float4 bb = *reinterpret_cast<const float4*>(bias + col0 + n0 + j);
            float4 v = make_float4(acc[i][j+0] + bb.x, acc[i][j+1] + bb.y,
                                   acc[i][j+2] + bb.z, acc[i][j+3] + bb.w);
            *reinterpret_cast<float4*>(o + j) = v;
        }
    }
}

// =============================================================================
extern "C" void kernel_launch(void* const* d_in, const int* in_sizes, int n_in,
                              void* d_out, int out_size)
{
    const int*   src       = (const int*)  d_in[0];
    const int*   trg       = (const int*)  d_in[1];
    const float* src_embed = (const float*)d_in[2];
    const float* trg_embed = (const float*)d_in[3];
    const float* eWih  = (const float*)d_in[4];
    const float* eWhh  = (const float*)d_in[5];
    const float* eBih  = (const float*)d_in[6];
    const float* eBhh  = (const float*)d_in[7];
    const float* d0Wih = (const float*)d_in[8];
    const float* d0Whh = (const float*)d_in[9];
    const float* d0Bih = (const float*)d_in[10];
    const float* d0Bhh = (const float*)d_in[11];
    const float* d1Wih = (const float*)d_in[12];
    const float* d1Whh = (const float*)d_in[13];
    const float* d1Bih = (const float*)d_in[14];
    const float* d1Bhh = (const float*)d_in[15];
    const float* attnW = (const float*)d_in[16];
    const float* attnB = (const float*)d_in[17];
    const float* vW    = (const float*)d_in[18];
    // d_in[19] = v_b : constant shift, cancels in softmax
    const float* fcW   = (const float*)d_in[20];
    const float* fcB   = (const float*)d_in[21];
    float* out = (float*)d_out;

    k_encoder<<<NBLK, NTHR>>>(src, trg, src_embed, trg_embed,
                              eWih, eWhh, eBih, eBhh,
                              d0Wih, d0Bih, attnW, attnB);
    k_decoder<<<NBLK, NTHR>>>(attnW, vW, d0Wih, d0Whh, d0Bhh,
                              d1Wih, d1Whh, d1Bih, d1Bhh);
    k_zero<<<(B_*V_ + 255)/256, 256>>>(out);
    k_fc<<<dim3(V_/128, (M_FC + 127)/128), 256>>>(fcW, fcB, out);
}

// round 5
// speedup vs baseline: 3.1055x; 3.1055x over previous
#include <cuda_runtime.h>
#include <cuda_bf16.h>
#include <math.h>
#include <stdint.h>

// Problem dims
#define B_  32
#define S_  128
#define T_  64
#define E_  64
#define H_  512
#define V_  32000
#define G3  1536            // 3*H
#define TD  63              // decoder steps (T-1)
#define M_FC (TD*B_)        // 2016 rows for final GEMM

#define NBLK  128           // persistent grid: 1 block/SM, one j-group of 4 each
#define NTHR  256
#define NWARP (NBLK*(NTHR/32))

// ---------------- scratch (device globals; no allocation allowed) -------------
__device__ float g_srcET [S_*E_*B_];          // [s][k][b]
__device__ float g_trgET [TD*E_*B_];          // [t][k][b]
__device__ float g_encGI [S_*G3*B_];          // [s][jg][b]  (incl. enc b_ih)
__device__ float g_giEmb [TD*G3*B_];          // [t][jg][b]  (emb part + d0 b_ih)
__device__ float g_encOut[S_*H_*B_];          // [s][j][b]
__device__ float g_encProj[S_*H_*B_];         // [s][k][b]  (incl. attn_b)
__device__ float g_hproj [H_*B_];
__device__ float g_scores[S_*B_];             // [s][b]
__device__ float g_ctx   [H_*B_];
__device__ float g_h0A[H_*B_], g_h0B[H_*B_];
__device__ float g_h1A[H_*B_], g_h1B[H_*B_];
__device__ float g_h1rm [M_FC*H_];            // row-major A for final GEMM

// ---------------- software grid barrier ---------------------------------------
__device__ unsigned int g_bar_count = 0;
__device__ volatile unsigned int g_bar_gen = 0;

__device__ __forceinline__ void grid_barrier() {
    __syncthreads();
    if (threadIdx.x == 0) {
        __threadfence();
        unsigned int gen = g_bar_gen;
        if (atomicInc(&g_bar_count, NBLK - 1) == NBLK - 1) {
            g_bar_gen = gen + 1;              // release
        } else {
            while (g_bar_gen == gen) { __nanosleep(16); }
        }
        __threadfence();
    }
    __syncthreads();
}

__device__ __forceinline__ float sigf(float x) { return 1.0f / (1.0f + __expf(-x)); }

// =============================================================================
// Kernel 1: embeddings, input-side GEMMs, encoder recurrent scan
// =============================================================================
__global__ void __launch_bounds__(NTHR, 1)
k_encoder(const int* __restrict__ src, const int* __restrict__ trg,
          const float* __restrict__ src_embed, const float* __restrict__ trg_embed,
          const float* __restrict__ eWih, const float* __restrict__ eWhh,
          const float* __restrict__ eBih, const float* __restrict__ eBhh,
          const float* __restrict__ d0Wih, const float* __restrict__ d0Bih)
{
    __shared__ float red[8][12][32];
    __shared__ float fin[12*32];

    const int tid  = threadIdx.x;
    const int lane = tid & 31;
    const int wid  = tid >> 5;
    const int gw   = blockIdx.x * (NTHR/32) + wid;
    const int gtid = blockIdx.x * NTHR + tid;
    const int NT   = NBLK * NTHR;
    const int j0   = blockIdx.x * 4;

    // ---- P0: gather embeddings into transposed [.,k,b] layout ----
    for (int i = gtid; i < S_*E_*B_; i += NT) {
        int b = i & 31, k = (i >> 5) & 63, s = i >> 11;
        g_srcET[i] = src_embed[(size_t)src[b*S_ + s]*E_ + k];
    }
    for (int i = gtid; i < TD*E_*B_; i += NT) {
        int b = i & 31, k = (i >> 5) & 63, t = i >> 11;
        g_trgET[i] = trg_embed[(size_t)trg[b*T_ + t]*E_ + k];
    }
    grid_barrier();

    // ---- P1: input-side GEMMs (jg quads per warp) ----
    for (int id = gw; id < S_*(G3/4); id += NWARP) {
        int s = id / (G3/4), jg0 = (id - s*(G3/4)) * 4;
        float a0 = eBih[jg0+0], a1 = eBih[jg0+1], a2 = eBih[jg0+2], a3 = eBih[jg0+3];
        const float* xe = g_srcET + (size_t)s*E_*B_ + lane;
        #pragma unroll 4
        for (int k = 0; k < E_; k++) {
            float x = xe[k*B_];
            a0 = fmaf(eWih[(size_t)(jg0+0)*E_ + k], x, a0);
            a1 = fmaf(eWih[(size_t)(jg0+1)*E_ + k], x, a1);
            a2 = fmaf(eWih[(size_t)(jg0+2)*E_ + k], x, a2);
            a3 = fmaf(eWih[(size_t)(jg0+3)*E_ + k], x, a3);
        }
        float* o = g_encGI + ((size_t)s*G3 + jg0)*B_ + lane;
        o[0] = a0; o[B_] = a1; o[2*B_] = a2; o[3*B_] = a3;
    }
    for (int id = gw; id < TD*(G3/4); id += NWARP) {
        int t = id / (G3/4), jg0 = (id - t*(G3/4)) * 4;
        float a0 = d0Bih[jg0+0], a1 = d0Bih[jg0+1], a2 = d0Bih[jg0+2], a3 = d0Bih[jg0+3];
        const float* xe = g_trgET + (size_t)t*E_*B_ + lane;
        #pragma unroll 4
        for (int k = 0; k < E_; k++) {
            float x = xe[k*B_];
            a0 = fmaf(d0Wih[(size_t)(jg0+0)*(E_+H_) + k], x, a0);
            a1 = fmaf(d0Wih[(size_t)(jg0+1)*(E_+H_) + k], x, a1);
            a2 = fmaf(d0Wih[(size_t)(jg0+2)*(E_+H_) + k], x, a2);
            a3 = fmaf(d0Wih[(size_t)(jg0+3)*(E_+H_) + k], x, a3);
        }
        float* o = g_giEmb + ((size_t)t*G3 + jg0)*B_ + lane;
        o[0] = a0; o[B_] = a1; o[2*B_] = a2; o[3*B_] = a3;
    }
    grid_barrier();

    // ---- P2: encoder recurrent scan (block owns j0..j0+3, warps split k) ----
    for (int t = 0; t < S_; t++) {
        float acc[12];
        #pragma unroll
        for (int i = 0; i < 12; i++) acc[i] = 0.0f;
        if (t > 0) {
            const float* hp = g_encOut + (size_t)(t-1)*H_*B_ + lane;
            const int k0 = wid * 64;
            #pragma unroll 4
            for (int k = k0; k < k0 + 64; k++) {
                float hv = hp[(size_t)k*B_];
                #pragma unroll
                for (int g = 0; g < 3; g++)
                    #pragma unroll
                    for (int jr = 0; jr < 4; jr++)
                        acc[g*4+jr] = fmaf(eWhh[(size_t)(g*H_ + j0 + jr)*H_ + k], hv, acc[g*4+jr]);
            }
        }
        #pragma unroll
        for (int i = 0; i < 12; i++) red[wid][i][lane] = acc[i];
        __syncthreads();
        for (int idx = tid; idx < 12*32; idx += NTHR) {
            int i = idx >> 5, b = idx & 31;
            float s = 0.0f;
            #pragma unroll
            for (int w = 0; w < 8; w++) s += red[w][i][b];
            fin[idx] = s;
        }
        __syncthreads();
        if (tid < 128) {
            int jr = tid >> 5, b = lane, j = j0 + jr;
            const float* gi = g_encGI + (size_t)t*G3*B_;
            float gir = gi[(size_t)j*B_ + b];
            float giz = gi[(size_t)(H_ + j)*B_ + b];
            float gin = gi[(size_t)(2*H_ + j)*B_ + b];
            float ghr = eBhh[j]        + fin[(0*4+jr)*32 + b];
            float ghz = eBhh[H_ + j]   + fin[(1*4+jr)*32 + b];
            float ghn = eBhh[2*H_ + j] + fin[(2*4+jr)*32 + b];
            float hprev = (t > 0) ? g_encOut[((size_t)(t-1)*H_ + j)*B_ + b] : 0.0f;
            float r = sigf(gir + ghr);
            float z = sigf(giz + ghz);
            float n = tanhf(gin + r*ghn);
            g_encOut[((size_t)t*H_ + j)*B_ + b] = (1.0f - z)*n + z*hprev;
        }
        grid_barrier();
    }
}

// =============================================================================
// Kernel 2: encProj[s][k][b] = attn_W[:,H:2H] @ enc_outs[s] + attn_b
// =============================================================================
__global__ void __launch_bounds__(NTHR, 1)
k_encproj(const float* __restrict__ attnW, const float* __restrict__ attnB)
{
    const int s    = blockIdx.x;
    const int lane = threadIdx.x & 31;
    const int wid  = threadIdx.x >> 5;
    const float* eo = g_encOut + (size_t)s*H_*B_ + lane;

    for (int jt = 0; jt < 4; jt++) {
        const int jb = wid*64 + jt*16;
        float acc[16];
        #pragma unroll
        for (int u = 0; u < 16; u++) acc[u] = attnB[jb + u];
        #pragma unroll 4
        for (int k = 0; k < H_; k++) {
            float hv = eo[(size_t)k*B_];
            #pragma unroll
            for (int u = 0; u < 16; u++)
                acc[u] = fmaf(attnW[(size_t)(jb+u)*(2*H_) + H_ + k], hv, acc[u]);
        }
        #pragma unroll
        for (int u = 0; u < 16; u++)
            g_encProj[((size_t)s*H_ + jb + u)*B_ + lane] = acc[u];
    }
}

// =============================================================================
// Kernel 3: decoder scan (5 grid barriers per step)
// =============================================================================
__global__ void __launch_bounds__(NTHR, 1)
k_decoder(const float* __restrict__ attnW, const float* __restrict__ vW,
          const float* __restrict__ d0Wih, const float* __restrict__ d0Whh,
          const float* __restrict__ d0Bhh,
          const float* __restrict__ d1Wih, const float* __restrict__ d1Whh,
          const float* __restrict__ d1Bih, const float* __restrict__ d1Bhh)
{
    __shared__ float red[8][24][32];     // 24 KB
    __shared__ float wsm[S_][32];        // 16 KB softmax weights
    __shared__ float pmax[8][32], psum[8][32];
    __shared__ float fin[24*32];         // 3 KB

    const int tid  = threadIdx.x;
    const int lane = tid & 31;
    const int wid  = tid >> 5;
    const int bi   = blockIdx.x;         // 0..127
    const int j0   = bi * 4;
    const int k0   = wid * 64;
    const float* encLast = g_encOut + (size_t)(S_-1)*H_*B_;

    for (int t = 0; t < TD; t++) {
        const float* h0in = (t == 0) ? encLast : ((t & 1) ? g_h0B : g_h0A);
        const float* h1in = (t == 0) ? encLast : ((t & 1) ? g_h1B : g_h1A);
        float* h0out = (t & 1) ? g_h0A : g_h0B;
        float* h1out = (t & 1) ? g_h1A : g_h1B;

        // ---- phase a: hproj[j0..j0+3] = attn_W[:,0:H] @ h1 ----
        {
            float acc[4] = {0.f, 0.f, 0.f, 0.f};
            const float* hp = h1in + lane;
            #pragma unroll 4
            for (int k = k0; k < k0 + 64; k++) {
                float hv = hp[(size_t)k*B_];
                #pragma unroll
                for (int r = 0; r < 4; r++)
                    acc[r] = fmaf(attnW[(size_t)(j0+r)*(2*H_) + k], hv, acc[r]);
            }
            #pragma unroll
            for (int r = 0; r < 4; r++) red[wid][r][lane] = acc[r];
            __syncthreads();
            if (tid < 128) {
                int r = tid >> 5, b = lane;
                float s = 0.0f;
                #pragma unroll
                for (int w = 0; w < 8; w++) s += red[w][r][b];
                g_hproj[(size_t)(j0+r)*B_ + b] = s;
            }
        }
        grid_barrier();

        // ---- phase b: scores[s=bi][b] = sum_k v[k] tanh(hproj + encProj) ----
        {
            float acc = 0.0f;
            const float* hp = g_hproj + lane;
            const float* ep = g_encProj + (size_t)bi*H_*B_ + lane;
            #pragma unroll 4
            for (int k = k0; k < k0 + 64; k++) {
                float e = tanhf(hp[(size_t)k*B_] + ep[(size_t)k*B_]);
                acc = fmaf(vW[k], e, acc);
            }
            red[wid][0][lane] = acc;
            __syncthreads();
            if (tid < 32) {
                float s = 0.0f;
                #pragma unroll
                for (int w = 0; w < 8; w++) s += red[w][0][tid];
                g_scores[bi*B_ + tid] = s;
            }
        }
        grid_barrier();

        // ---- phase cd: softmax (redundant per block) + ctx[j0..j0+3] ----
        {
            // pass 1: max over this warp's 16 s
            float m = -1e30f;
            #pragma unroll
            for (int si = 0; si < 16; si++)
                m = fmaxf(m, g_scores[(wid*16 + si)*B_ + lane]);
            pmax[wid][lane] = m;
            __syncthreads();
            float bm = pmax[0][lane];
            #pragma unroll
            for (int w = 1; w < 8; w++) bm = fmaxf(bm, pmax[w][lane]);
            // pass 2: exp + partial sum
            float ps = 0.0f;
            #pragma unroll
            for (int si = 0; si < 16; si++) {
                int s = wid*16 + si;
                float e = __expf(g_scores[s*B_ + lane] - bm);
                wsm[s][lane] = e;
                ps += e;
            }
            psum[wid][lane] = ps;
            __syncthreads();
            float tot = psum[0][lane];
            #pragma unroll
            for (int w = 1; w < 8; w++) tot += psum[w][lane];
            float inv = 1.0f / tot;
            // ctx partials over this warp's s-chunk
            float c[4] = {0.f, 0.f, 0.f, 0.f};
            #pragma unroll
            for (int si = 0; si < 16; si++) {
                int s = wid*16 + si;
                float wv = wsm[s][lane];
                #pragma unroll
                for (int jr = 0; jr < 4; jr++)
                    c[jr] = fmaf(wv, g_encOut[((size_t)s*H_ + j0 + jr)*B_ + lane], c[jr]);
            }
            #pragma unroll
            for (int jr = 0; jr < 4; jr++) red[wid][jr][lane] = c[jr];
            __syncthreads();
            if (tid < 128) {
                int jr = tid >> 5, b = lane;
                float s = 0.0f;
                #pragma unroll
                for (int w = 0; w < 8; w++) s += red[w][jr][b];
                g_ctx[(size_t)(j0+jr)*B_ + b] = s * inv;   // inv valid: lane==b
            }
        }
        grid_barrier();

        // ---- phase e: GRU layer 0 ----
        {
            float acc[24];
            #pragma unroll
            for (int i = 0; i < 24; i++) acc[i] = 0.0f;
            const float* cp = g_ctx + lane;
            const float* hp = h0in + lane;
            #pragma unroll 2
            for (int k = k0; k < k0 + 64; k++) {
                float cv = cp[(size_t)k*B_];
                float hv = hp[(size_t)k*B_];
                #pragma unroll
                for (int g = 0; g < 3; g++)
                    #pragma unroll
                    for (int jr = 0; jr < 4; jr++) {
                        acc[g*4+jr]    = fmaf(d0Wih[(size_t)(g*H_ + j0 + jr)*(E_+H_) + E_ + k], cv, acc[g*4+jr]);
                        acc[12+g*4+jr] = fmaf(d0Whh[(size_t)(g*H_ + j0 + jr)*H_ + k],           hv, acc[12+g*4+jr]);
                    }
            }
            #pragma unroll
            for (int i = 0; i < 24; i++) red[wid][i][lane] = acc[i];
            __syncthreads();
            for (int idx = tid; idx < 24*32; idx += NTHR) {
                int i = idx >> 5, b = idx & 31;
                float s = 0.0f;
                #pragma unroll
                for (int w = 0; w < 8; w++) s += red[w][i][b];
                fin[idx] = s;
            }
            __syncthreads();
            if (tid < 128) {
                int jr = tid >> 5, b = lane, j = j0 + jr;
                const float* gie = g_giEmb + (size_t)t*G3*B_;
                float gir = gie[(size_t)j*B_ + b]        + fin[(0*4+jr)*32 + b];
                float giz = gie[(size_t)(H_+j)*B_ + b]   + fin[(1*4+jr)*32 + b];
                float gin = gie[(size_t)(2*H_+j)*B_ + b] + fin[(2*4+jr)*32 + b];
                float ghr = d0Bhh[j]        + fin[(12+0*4+jr)*32 + b];
                float ghz = d0Bhh[H_+j]     + fin[(12+1*4+jr)*32 + b];
                float ghn = d0Bhh[2*H_+j]   + fin[(12+2*4+jr)*32 + b];
                float r = sigf(gir + ghr);
                float z = sigf(giz + ghz);
                float n = tanhf(gin + r*ghn);
                h0out[(size_t)j*B_ + b] = (1.0f - z)*n + z*h0in[(size_t)j*B_ + b];
            }
        }
        grid_barrier();

        // ---- phase f: GRU layer 1 ----
        {
            float acc[24];
            #pragma unroll
            for (int i = 0; i < 24; i++) acc[i] = 0.0f;
            const float* xp = h0out + lane;
            const float* hp = h1in + lane;
            #pragma unroll 2
            for (int k = k0; k < k0 + 64; k++) {
                float xv = xp[(size_t)k*B_];
                float hv = hp[(size_t)k*B_];
                #pragma unroll
                for (int g = 0; g < 3; g++)
                    #pragma unroll
                    for (int jr = 0; jr < 4; jr++) {
                        acc[g*4+jr]    = fmaf(d1Wih[(size_t)(g*H_ + j0 + jr)*H_ + k], xv, acc[g*4+jr]);
                        acc[12+g*4+jr] = fmaf(d1Whh[(size_t)(g*H_ + j0 + jr)*H_ + k], hv, acc[12+g*4+jr]);
                    }
            }
            #pragma unroll
            for (int i = 0; i < 24; i++) red[wid][i][lane] = acc[i];
            __syncthreads();
            for (int idx = tid; idx < 24*32; idx += NTHR) {
                int i = idx >> 5, b = idx & 31;
                float s = 0.0f;
                #pragma unroll
                for (int w = 0; w < 8; w++) s += red[w][i][b];
                fin[idx] = s;
            }
            __syncthreads();
            if (tid < 128) {
                int jr = tid >> 5, b = lane, j = j0 + jr;
                float gir = d1Bih[j]      + fin[(0*4+jr)*32 + b];
                float giz = d1Bih[H_+j]   + fin[(1*4+jr)*32 + b];
                float gin = d1Bih[2*H_+j] + fin[(2*4+jr)*32 + b];
                float ghr = d1Bhh[j]      + fin[(12+0*4+jr)*32 + b];
                float ghz = d1Bhh[H_+j]   + fin[(12+1*4+jr)*32 + b];
                float ghn = d1Bhh[2*H_+j] + fin[(12+2*4+jr)*32 + b];
                float r = sigf(gir + ghr);
                float z = sigf(giz + ghz);
                float n = tanhf(gin + r*ghn);
                float h1v = (1.0f - z)*n + z*h1in[(size_t)j*B_ + b];
                h1out[(size_t)j*B_ + b] = h1v;
                g_h1rm[(size_t)(t*B_ + b)*H_ + j] = h1v;
            }
        }
        grid_barrier();
    }
}

// =============================================================================
// Kernel 4: zero the t=0 output slice
// =============================================================================
__global__ void k_zero(float* __restrict__ out) {
    int i = blockIdx.x * blockDim.x + threadIdx.x;
    if (i < B_*V_) {
        int b = i / V_, v = i - b*V_;
        out[(size_t)b*T_*V_ + v] = 0.0f;
    }
}

// =============================================================================
// Kernel 5: final projection  C[2016,32000] = h1_all @ fc_W^T + fc_b
// =============================================================================
__global__ void __launch_bounds__(256)
k_fc(const float* __restrict__ W, const float* __restrict__ bias,
     float* __restrict__ out)
{
    __shared__ float As[16][128];
    __shared__ float Bs[16][128];
    const int tid  = threadIdx.x;
    const int row0 = blockIdx.y * 128;
    const int col0 = blockIdx.x * 128;

    const int warp = tid >> 5, lane = tid & 31;
    const int m0 = (warp & 3) * 32 + (lane & 3) * 8;
    const int n0 = (warp >> 2) * 64 + (lane >> 2) * 8;

    float acc[8][8];
    #pragma unroll
    for (int i = 0; i < 8; i++)
        #pragma unroll
        for (int j = 0; j < 8; j++) acc[i][j] = 0.0f;

    const int lr = tid >> 2;           // 0..63
    const int lk = (tid & 3) * 4;      // 0,4,8,12

    for (int kk0 = 0; kk0 < H_; kk0 += 16) {
        #pragma unroll
        for (int h = 0; h < 2; h++) {
            int r = row0 + lr + h*64;
            float4 v = make_float4(0.f, 0.f, 0.f, 0.f);
            if (r < M_FC)
                v = *reinterpret_cast<const float4*>(g_h1rm + (size_t)r*H_ + kk0 + lk);
            As[lk+0][lr + h*64] = v.x;
            As[lk+1][lr + h*64] = v.y;
            As[lk+2][lr + h*64] = v.z;
            As[lk+3][lr + h*64] = v.w;
        }
        #pragma unroll
        for (int h = 0; h < 2; h++) {
            int c = col0 + lr + h*64;
            float4 v = *reinterpret_cast<const float4*>(W + (size_t)c*H_ + kk0 + lk);
            Bs[lk+0][lr + h*64] = v.x;
            Bs[lk+1][lr + h*64] = v.y;
            Bs[lk+2][lr + h*64] = v.z;
            Bs[lk+3][lr + h*64] = v.w;
        }
        __syncthreads();
        #pragma unroll
        for (int kk = 0; kk < 16; kk++) {
            float4 a0 = *reinterpret_cast<const float4*>(&As[kk][m0]);
            float4 a1 = *reinterpret_cast<const float4*>(&As[kk][m0+4]);
            float4 b0 = *reinterpret_cast<const float4*>(&Bs[kk][n0]);
            float4 b1 = *reinterpret_cast<const float4*>(&Bs[kk][n0+4]);
            float av[8] = {a0.x,a0.y,a0.z,a0.w,a1.x,a1.y,a1.z,a1.w};
            float bv[8] = {b0.x,b0.y,b0.z,b0.w,b1.x,b1.y,b1.z,b1.w};
            #pragma unroll
            for (int i = 0; i < 8; i++)
                #pragma unroll
                for (int j = 0; j < 8; j++)
                    acc[i][j] = fmaf(av[i], bv[j], acc[i][j]);
        }
        __syncthreads();
    }

    #pragma unroll
    for (int i = 0; i < 8; i++) {
        int r = row0 + m0 + i;
        if (r >= M_FC) continue;
        int b = r & 31, t = r >> 5;
        float* o = out + (size_t)b*T_*V_ + (size_t)(t+1)*V_ + col0 + n0;
        #pragma unroll
        for (int j = 0; j < 8; j += 4) {
            float4 bb = *reinterpret_cast<const float4*>(bias + col0 + n0 + j);
            float4 v = make_float4(acc[i][j+0] + bb.x, acc[i][j+1] + bb.y,
                                   acc[i][j+2] + bb.z, acc[i][j+3] + bb.w);
            *reinterpret_cast<float4*>(o + j) = v;
        }
    }
}

// =============================================================================
extern "C" void kernel_launch(void* const* d_in, const int* in_sizes, int n_in,
                              void* d_out, int out_size)
{
    const int*   src       = (const int*)  d_in[0];
    const int*   trg       = (const int*)  d_in[1];
    const float* src_embed = (const float*)d_in[2];
    const float* trg_embed = (const float*)d_in[3];
    const float* eWih  = (const float*)d_in[4];
    const float* eWhh  = (const float*)d_in[5];
    const float* eBih  = (const float*)d_in[6];
    const float* eBhh  = (const float*)d_in[7];
    const float* d0Wih = (const float*)d_in[8];
    const float* d0Whh = (const float*)d_in[9];
    const float* d0Bih = (const float*)d_in[10];
    const float* d0Bhh = (const float*)d_in[11];
    const float* d1Wih = (const float*)d_in[12];
    const float* d1Whh = (const float*)d_in[13];
    const float* d1Bih = (const float*)d_in[14];
    const float* d1Bhh = (const float*)d_in[15];
    const float* attnW = (const float*)d_in[16];
    const float* attnB = (const float*)d_in[17];
    const float* vW    = (const float*)d_in[18];
    // d_in[19] = v_b : constant shift, cancels in softmax
    const float* fcW   = (const float*)d_in[20];
    const float* fcB   = (const float*)d_in[21];
    float* out = (float*)d_out;

    k_encoder<<<NBLK, NTHR>>>(src, trg, src_embed, trg_embed,
                              eWih, eWhh, eBih, eBhh, d0Wih, d0Bih);
    k_encproj<<<NBLK, NTHR>>>(attnW, attnB);
    k_decoder<<<NBLK, NTHR>>>(attnW, vW, d0Wih, d0Whh, d0Bhh,
                              d1Wih, d1Whh, d1Bih, d1Bhh);
    k_zero<<<(B_*V_ + 255)/256, 256>>>(out);
    k_fc<<<dim3(V_/128, (M_FC + 127)/128), 256>>>(fcW, fcB, out);
}

// round 7
// speedup vs baseline: 3.9451x; 1.2704x over previous
#include <cuda_runtime.h>
#include <cuda_bf16.h>
#include <math.h>
#include <stdint.h>

// Problem dims
#define B_  32
#define S_  128
#define T_  64
#define E_  64
#define H_  512
#define V_  32000
#define G3  1536            // 3*H
#define TD  63              // decoder steps (T-1)
#define M_FC (TD*B_)        // 2016 rows for final GEMM

#define NBLK  128           // persistent grid: 1 block/SM
#define NTHR  256
#define NWARP (NBLK*(NTHR/32))

// ---------------- scratch (device globals; no allocation allowed) -------------
__device__ float g_srcET [S_*E_*B_];          // [s][k][b]
__device__ float g_trgET [TD*E_*B_];          // [t][k][b]
__device__ float g_encGI [S_*G3*B_];          // [s][jg][b]  (incl. enc b_ih)
__device__ float g_giEmb [TD*G3*B_];          // [t][jg][b]  (emb part + d0 b_ih)
__device__ float g_encOut[S_*H_*B_];          // [s][j][b]
__device__ float g_encProj[S_*H_*B_];         // [s][j][b]  (incl. attn_b)
__device__ float g_hproj [H_*B_];
__device__ float g_scores[S_*B_];             // [s][b]
__device__ float g_ctx   [H_*B_];
__device__ float g_h0A[H_*B_], g_h0B[H_*B_];
__device__ float g_h1A[H_*B_], g_h1B[H_*B_];
__device__ float g_h1rm [M_FC*H_];            // row-major A for final GEMM

// ---------------- fast software grid barrier ----------------------------------
// Arrivals: RED-style atomicAdd (result unused) to a ping-pong counter.
// Block 0 detects full count, resets that counter, bumps gen. Others poll gen.
// Counters return to 0 after every barrier -> state is replay-safe; gen is
// monotonic and re-read at kernel entry.
__device__ unsigned int g_cnt2[2];
__device__ volatile unsigned int g_genv;

__device__ __forceinline__ void gbar(unsigned int& mygen, unsigned int& par) {
    __syncthreads();
    if (threadIdx.x == 0) {
        __threadfence();
        unsigned int p = par;
        atomicAdd(&g_cnt2[p], 1u);                 // result unused -> RED
        if (blockIdx.x == 0) {
            volatile unsigned int* c = (volatile unsigned int*)&g_cnt2[p];
            while (*c < NBLK) __nanosleep(8);
            *c = 0;                                // safe: all arrived; reused 2 barriers later
            __threadfence();
            g_genv = mygen + 1u;
        } else {
            while (g_genv == mygen) __nanosleep(8);
        }
        __threadfence();
    }
    __syncthreads();
    mygen += 1u;
    par ^= 1u;
}

__device__ __forceinline__ float sigf(float x) { return 1.0f / (1.0f + __expf(-x)); }
__device__ __forceinline__ float tanha(float x) {
    float y; asm("tanh.approx.f32 %0, %1;" : "=f"(y) : "f"(x)); return y;
}

// =============================================================================
// Kernel 1: embeddings, input-side GEMMs, encoder recurrent scan
// =============================================================================
__global__ void __launch_bounds__(NTHR, 1)
k_encoder(const int* __restrict__ src, const int* __restrict__ trg,
          const float* __restrict__ src_embed, const float* __restrict__ trg_embed,
          const float* __restrict__ eWih, const float* __restrict__ eWhh,
          const float* __restrict__ eBih, const float* __restrict__ eBhh,
          const float* __restrict__ d0Wih, const float* __restrict__ d0Bih)
{
    __shared__ float4 sWe[12*128];        // eWhh rows (3 gates x 4 j) over k, 24 KB
    __shared__ float red[8][12][32];      // 12 KB
    __shared__ float fin[12*32];          // 1.5 KB

    const int tid  = threadIdx.x;
    const int lane = tid & 31;
    const int wid  = tid >> 5;
    const int gw   = blockIdx.x * (NTHR/32) + wid;
    const int gtid = blockIdx.x * NTHR + tid;
    const int NT   = NBLK * NTHR;
    const int j0   = blockIdx.x * 4;

    unsigned int mygen = g_genv;
    unsigned int par   = 0;

    // stage eWhh rows for this block's 4 j's
    for (int idx = tid; idx < 12*128; idx += NTHR) {
        int i = idx >> 7, kg = idx & 127;
        int g = i >> 2, jr = i & 3;
        sWe[idx] = *reinterpret_cast<const float4*>(
            eWhh + (size_t)(g*H_ + j0 + jr)*H_ + kg*4);
    }

    // ---- P0: gather embeddings into transposed [.,k,b] layout ----
    for (int i = gtid; i < S_*E_*B_; i += NT) {
        int b = i & 31, k = (i >> 5) & 63, s = i >> 11;
        g_srcET[i] = src_embed[(size_t)src[b*S_ + s]*E_ + k];
    }
    for (int i = gtid; i < TD*E_*B_; i += NT) {
        int b = i & 31, k = (i >> 5) & 63, t = i >> 11;
        g_trgET[i] = trg_embed[(size_t)trg[b*T_ + t]*E_ + k];
    }
    gbar(mygen, par);

    // ---- P1: input-side GEMMs (jg quads per warp, float4 weights) ----
    for (int id = gw; id < S_*(G3/4); id += NWARP) {
        int s = id / (G3/4), jg0 = (id - s*(G3/4)) * 4;
        float a[4] = {eBih[jg0+0], eBih[jg0+1], eBih[jg0+2], eBih[jg0+3]};
        const float* xe = g_srcET + (size_t)s*E_*B_ + lane;
        #pragma unroll
        for (int kg = 0; kg < 16; kg++) {
            float x0 = xe[(kg*4+0)*B_], x1 = xe[(kg*4+1)*B_];
            float x2 = xe[(kg*4+2)*B_], x3 = xe[(kg*4+3)*B_];
            #pragma unroll
            for (int r = 0; r < 4; r++) {
                float4 w = *reinterpret_cast<const float4*>(eWih + (size_t)(jg0+r)*E_ + kg*4);
                a[r] = fmaf(w.x,x0,fmaf(w.y,x1,fmaf(w.z,x2,fmaf(w.w,x3,a[r]))));
            }
        }
        float* o = g_encGI + ((size_t)s*G3 + jg0)*B_ + lane;
        o[0] = a[0]; o[B_] = a[1]; o[2*B_] = a[2]; o[3*B_] = a[3];
    }
    for (int id = gw; id < TD*(G3/4); id += NWARP) {
        int t = id / (G3/4), jg0 = (id - t*(G3/4)) * 4;
        float a[4] = {d0Bih[jg0+0], d0Bih[jg0+1], d0Bih[jg0+2], d0Bih[jg0+3]};
        const float* xe = g_trgET + (size_t)t*E_*B_ + lane;
        #pragma unroll
        for (int kg = 0; kg < 16; kg++) {
            float x0 = xe[(kg*4+0)*B_], x1 = xe[(kg*4+1)*B_];
            float x2 = xe[(kg*4+2)*B_], x3 = xe[(kg*4+3)*B_];
            #pragma unroll
            for (int r = 0; r < 4; r++) {
                float4 w = *reinterpret_cast<const float4*>(d0Wih + (size_t)(jg0+r)*(E_+H_) + kg*4);
                a[r] = fmaf(w.x,x0,fmaf(w.y,x1,fmaf(w.z,x2,fmaf(w.w,x3,a[r]))));
            }
        }
        float* o = g_giEmb + ((size_t)t*G3 + jg0)*B_ + lane;
        o[0] = a[0]; o[B_] = a[1]; o[2*B_] = a[2]; o[3*B_] = a[3];
    }
    gbar(mygen, par);

    // ---- P2: encoder recurrent scan (block owns j0..j0+3, warps split k) ----
    for (int t = 0; t < S_; t++) {
        float acc[12];
        #pragma unroll
        for (int i = 0; i < 12; i++) acc[i] = 0.0f;
        if (t > 0) {
            const float* hp = g_encOut + (size_t)(t-1)*H_*B_ + lane;
            const int kg0 = wid * 16;
            #pragma unroll 2
            for (int kg = kg0; kg < kg0 + 16; kg++) {
                float h0 = hp[(size_t)(kg*4+0)*B_];
                float h1 = hp[(size_t)(kg*4+1)*B_];
                float h2 = hp[(size_t)(kg*4+2)*B_];
                float h3 = hp[(size_t)(kg*4+3)*B_];
                #pragma unroll
                for (int i = 0; i < 12; i++) {
                    float4 w = sWe[i*128 + kg];
                    acc[i] = fmaf(w.x,h0,fmaf(w.y,h1,fmaf(w.z,h2,fmaf(w.w,h3,acc[i]))));
                }
            }
        }
        #pragma unroll
        for (int i = 0; i < 12; i++) red[wid][i][lane] = acc[i];
        __syncthreads();
        for (int idx = tid; idx < 12*32; idx += NTHR) {
            int i = idx >> 5, b = idx & 31;
            float s = 0.0f;
            #pragma unroll
            for (int w = 0; w < 8; w++) s += red[w][i][b];
            fin[idx] = s;
        }
        __syncthreads();
        if (tid < 128) {
            int jr = tid >> 5, b = lane, j = j0 + jr;
            const float* gi = g_encGI + (size_t)t*G3*B_;
            float gir = gi[(size_t)j*B_ + b];
            float giz = gi[(size_t)(H_ + j)*B_ + b];
            float gin = gi[(size_t)(2*H_ + j)*B_ + b];
            float ghr = eBhh[j]        + fin[(0*4+jr)*32 + b];
            float ghz = eBhh[H_ + j]   + fin[(1*4+jr)*32 + b];
            float ghn = eBhh[2*H_ + j] + fin[(2*4+jr)*32 + b];
            float hprev = (t > 0) ? g_encOut[((size_t)(t-1)*H_ + j)*B_ + b] : 0.0f;
            float r = sigf(gir + ghr);
            float z = sigf(giz + ghz);
            float n = tanhf(gin + r*ghn);
            g_encOut[((size_t)t*H_ + j)*B_ + b] = (1.0f - z)*n + z*hprev;
        }
        gbar(mygen, par);
    }
}

// =============================================================================
// Kernel 2: encProj = attn_W[:,H:2H] @ enc_outs + attn_b   (2D split 16sx8j)
// =============================================================================
__global__ void __launch_bounds__(NTHR, 1)
k_encproj(const float* __restrict__ attnW, const float* __restrict__ attnB)
{
    extern __shared__ float4 sWp[];      // 64 rows x 128 float4 = 128 KB
    const int tid  = threadIdx.x;
    const int lane = tid & 31;
    const int wid  = tid >> 5;
    const int sg   = blockIdx.x >> 3;    // 16 s-groups of 8
    const int jg   = blockIdx.x & 7;     // 8 j-groups of 64

    for (int idx = tid; idx < 64*128; idx += NTHR) {
        int r = idx >> 7, kg = idx & 127;
        sWp[idx] = *reinterpret_cast<const float4*>(
            attnW + (size_t)(jg*64 + r)*(2*H_) + H_ + kg*4);
    }
    __syncthreads();

    const int r0 = wid * 8;              // this warp's 8 local rows
    for (int s = sg*8; s < sg*8 + 8; s++) {
        float acc[8];
        #pragma unroll
        for (int r = 0; r < 8; r++) acc[r] = attnB[jg*64 + r0 + r];
        const float* eo = g_encOut + (size_t)s*H_*B_ + lane;
        #pragma unroll 2
        for (int kg = 0; kg < 128; kg++) {
            float h0 = eo[(size_t)(kg*4+0)*B_];
            float h1 = eo[(size_t)(kg*4+1)*B_];
            float h2 = eo[(size_t)(kg*4+2)*B_];
            float h3 = eo[(size_t)(kg*4+3)*B_];
            #pragma unroll
            for (int r = 0; r < 8; r++) {
                float4 w = sWp[(r0 + r)*128 + kg];
                acc[r] = fmaf(w.x,h0,fmaf(w.y,h1,fmaf(w.z,h2,fmaf(w.w,h3,acc[r]))));
            }
        }
        #pragma unroll
        for (int r = 0; r < 8; r++)
            g_encProj[((size_t)s*H_ + jg*64 + r0 + r)*B_ + lane] = acc[r];
    }
}

// =============================================================================
// Kernel 3: decoder scan (weights smem-staged, 5 grid barriers per step)
// =============================================================================
// dynamic smem layout (floats):
#define D_SA    0                         // attnW left, 4x512
#define D_WI0   (D_SA   + 4*512)          // d0Wih H-part, 12x512
#define D_WH0   (D_WI0  + 12*512)
#define D_WI1   (D_WH0  + 12*512)
#define D_WH1   (D_WI1  + 12*512)
#define D_RED   (D_WH1  + 12*512)         // 8*24*32
#define D_WSM   (D_RED  + 8*24*32)        // 128*32
#define D_PMAX  (D_WSM  + 128*32)         // 8*32
#define D_PSUM  (D_PMAX + 8*32)           // 8*32
#define D_FIN   (D_PSUM + 8*32)           // 24*32
#define D_TOTAL (D_FIN  + 24*32)          // floats

__global__ void __launch_bounds__(NTHR, 1)
k_decoder(const float* __restrict__ attnW, const float* __restrict__ vW,
          const float* __restrict__ d0Wih, const float* __restrict__ d0Whh,
          const float* __restrict__ d0Bhh,
          const float* __restrict__ d1Wih, const float* __restrict__ d1Whh,
          const float* __restrict__ d1Bih, const float* __restrict__ d1Bhh)
{
    extern __shared__ float dsm[];
    float4* sA   = reinterpret_cast<float4*>(dsm + D_SA);
    float4* sWi0 = reinterpret_cast<float4*>(dsm + D_WI0);
    float4* sWh0 = reinterpret_cast<float4*>(dsm + D_WH0);
    float4* sWi1 = reinterpret_cast<float4*>(dsm + D_WI1);
    float4* sWh1 = reinterpret_cast<float4*>(dsm + D_WH1);
    float*  red  = dsm + D_RED;     // [wid][i][lane] -> (wid*24+i)*32+lane
    float*  wsm  = dsm + D_WSM;     // [s][lane]
    float*  pmax = dsm + D_PMAX;
    float*  psum = dsm + D_PSUM;
    float*  fin  = dsm + D_FIN;

    const int tid  = threadIdx.x;
    const int lane = tid & 31;
    const int wid  = tid >> 5;
    const int bi   = blockIdx.x;
    const int j0   = bi * 4;
    const int kg0  = wid * 16;      // this warp's 16 k-groups (64 k)
    const float* encLast = g_encOut + (size_t)(S_-1)*H_*B_;

    unsigned int mygen = g_genv;
    unsigned int par   = 0;

    // ---- stage this block's weight rows ----
    for (int idx = tid; idx < 4*128; idx += NTHR) {
        int r = idx >> 7, kg = idx & 127;
        sA[idx] = *reinterpret_cast<const float4*>(attnW + (size_t)(j0+r)*(2*H_) + kg*4);
    }
    for (int idx = tid; idx < 12*128; idx += NTHR) {
        int i = idx >> 7, kg = idx & 127;
        int g = i >> 2, jr = i & 3;
        size_t row = (size_t)(g*H_ + j0 + jr);
        sWi0[idx] = *reinterpret_cast<const float4*>(d0Wih + row*(E_+H_) + E_ + kg*4);
        sWh0[idx] = *reinterpret_cast<const float4*>(d0Whh + row*H_ + kg*4);
        sWi1[idx] = *reinterpret_cast<const float4*>(d1Wih + row*H_ + kg*4);
        sWh1[idx] = *reinterpret_cast<const float4*>(d1Whh + row*H_ + kg*4);
    }
    __syncthreads();

    for (int t = 0; t < TD; t++) {
        const float* h0in = (t == 0) ? encLast : ((t & 1) ? g_h0B : g_h0A);
        const float* h1in = (t == 0) ? encLast : ((t & 1) ? g_h1B : g_h1A);
        float* h0out = (t & 1) ? g_h0A : g_h0B;
        float* h1out = (t & 1) ? g_h1A : g_h1B;

        // ---- phase a: hproj[j0..j0+3] = attn_W[:,0:H] @ h1 ----
        {
            float acc[4] = {0.f, 0.f, 0.f, 0.f};
            const float* hp = h1in + lane;
            #pragma unroll 2
            for (int kg = kg0; kg < kg0 + 16; kg++) {
                float h0 = hp[(size_t)(kg*4+0)*B_];
                float h1 = hp[(size_t)(kg*4+1)*B_];
                float h2 = hp[(size_t)(kg*4+2)*B_];
                float h3 = hp[(size_t)(kg*4+3)*B_];
                #pragma unroll
                for (int r = 0; r < 4; r++) {
                    float4 w = sA[r*128 + kg];
                    acc[r] = fmaf(w.x,h0,fmaf(w.y,h1,fmaf(w.z,h2,fmaf(w.w,h3,acc[r]))));
                }
            }
            #pragma unroll
            for (int r = 0; r < 4; r++) red[(wid*24 + r)*32 + lane] = acc[r];
            __syncthreads();
            if (tid < 128) {
                int r = tid >> 5, b = lane;
                float s = 0.0f;
                #pragma unroll
                for (int w = 0; w < 8; w++) s += red[(w*24 + r)*32 + b];
                g_hproj[(size_t)(j0+r)*B_ + b] = s;
            }
        }
        gbar(mygen, par);

        // ---- phase b: scores[s=bi][b] = sum_k v[k] tanh(hproj + encProj) ----
        {
            float acc = 0.0f;
            const float* hp = g_hproj + lane;
            const float* ep = g_encProj + (size_t)bi*H_*B_ + lane;
            #pragma unroll 4
            for (int k = kg0*4; k < kg0*4 + 64; k++) {
                float e = tanha(hp[(size_t)k*B_] + ep[(size_t)k*B_]);
                acc = fmaf(vW[k], e, acc);
            }
            red[(wid*24)*32 + lane] = acc;
            __syncthreads();
            if (tid < 32) {
                float s = 0.0f;
                #pragma unroll
                for (int w = 0; w < 8; w++) s += red[(w*24)*32 + tid];
                g_scores[bi*B_ + tid] = s;
            }
        }
        gbar(mygen, par);

        // ---- phase cd: softmax (redundant per block) + ctx[j0..j0+3] ----
        {
            float m = -1e30f;
            #pragma unroll
            for (int si = 0; si < 16; si++)
                m = fmaxf(m, g_scores[(wid*16 + si)*B_ + lane]);
            pmax[wid*32 + lane] = m;
            __syncthreads();
            float bm = pmax[lane];
            #pragma unroll
            for (int w = 1; w < 8; w++) bm = fmaxf(bm, pmax[w*32 + lane]);
            float ps = 0.0f;
            #pragma unroll
            for (int si = 0; si < 16; si++) {
                int s = wid*16 + si;
                float e = __expf(g_scores[s*B_ + lane] - bm);
                wsm[s*32 + lane] = e;
                ps += e;
            }
            psum[wid*32 + lane] = ps;
            __syncthreads();
            float tot = psum[lane];
            #pragma unroll
            for (int w = 1; w < 8; w++) tot += psum[w*32 + lane];
            float inv = 1.0f / tot;
            float c[4] = {0.f, 0.f, 0.f, 0.f};
            #pragma unroll
            for (int si = 0; si < 16; si++) {
                int s = wid*16 + si;
                float wv = wsm[s*32 + lane];
                #pragma unroll
                for (int jr = 0; jr < 4; jr++)
                    c[jr] = fmaf(wv, g_encOut[((size_t)s*H_ + j0 + jr)*B_ + lane], c[jr]);
            }
            #pragma unroll
            for (int jr = 0; jr < 4; jr++) red[(wid*24 + jr)*32 + lane] = c[jr];
            __syncthreads();
            if (tid < 128) {
                int jr = tid >> 5, b = lane;
                float s = 0.0f;
                #pragma unroll
                for (int w = 0; w < 8; w++) s += red[(w*24 + jr)*32 + b];
                g_ctx[(size_t)(j0+jr)*B_ + b] = s * inv;   // inv valid: lane==b
            }
        }
        gbar(mygen, par);

        // ---- phase e: GRU layer 0 ----
        {
            float acc[24];
            #pragma unroll
            for (int i = 0; i < 24; i++) acc[i] = 0.0f;
            const float* cp = g_ctx + lane;
            const float* hp = h0in + lane;
            for (int kg = kg0; kg < kg0 + 16; kg++) {
                float c0 = cp[(size_t)(kg*4+0)*B_], c1 = cp[(size_t)(kg*4+1)*B_];
                float c2 = cp[(size_t)(kg*4+2)*B_], c3 = cp[(size_t)(kg*4+3)*B_];
                float h0 = hp[(size_t)(kg*4+0)*B_], h1 = hp[(size_t)(kg*4+1)*B_];
                float h2 = hp[(size_t)(kg*4+2)*B_], h3 = hp[(size_t)(kg*4+3)*B_];
                #pragma unroll
                for (int i = 0; i < 12; i++) {
                    float4 wi = sWi0[i*128 + kg];
                    float4 wh = sWh0[i*128 + kg];
                    acc[i]    = fmaf(wi.x,c0,fmaf(wi.y,c1,fmaf(wi.z,c2,fmaf(wi.w,c3,acc[i]))));
                    acc[12+i] = fmaf(wh.x,h0,fmaf(wh.y,h1,fmaf(wh.z,h2,fmaf(wh.w,h3,acc[12+i]))));
                }
            }
            #pragma unroll
            for (int i = 0; i < 24; i++) red[(wid*24 + i)*32 + lane] = acc[i];
            __syncthreads();
            for (int idx = tid; idx < 24*32; idx += NTHR) {
                int i = idx >> 5, b = idx & 31;
                float s = 0.0f;
                #pragma unroll
                for (int w = 0; w < 8; w++) s += red[(w*24 + i)*32 + b];
                fin[idx] = s;
            }
            __syncthreads();
            if (tid < 128) {
                int jr = tid >> 5, b = lane, j = j0 + jr;
                const float* gie = g_giEmb + (size_t)t*G3*B_;
                float gir = gie[(size_t)j*B_ + b]        + fin[(0*4+jr)*32 + b];
                float giz = gie[(size_t)(H_+j)*B_ + b]   + fin[(1*4+jr)*32 + b];
                float gin = gie[(size_t)(2*H_+j)*B_ + b] + fin[(2*4+jr)*32 + b];
                float ghr = d0Bhh[j]      + fin[(12+0*4+jr)*32 + b];
                float ghz = d0Bhh[H_+j]   + fin[(12+1*4+jr)*32 + b];
                float ghn = d0Bhh[2*H_+j] + fin[(12+2*4+jr)*32 + b];
                float r = sigf(gir + ghr);
                float z = sigf(giz + ghz);
                float n = tanhf(gin + r*ghn);
                h0out[(size_t)j*B_ + b] = (1.0f - z)*n + z*h0in[(size_t)j*B_ + b];
            }
        }
        gbar(mygen, par);

        // ---- phase f: GRU layer 1 ----
        {
            float acc[24];
            #pragma unroll
            for (int i = 0; i < 24; i++) acc[i] = 0.0f;
            const float* xp = h0out + lane;
            const float* hp = h1in + lane;
            for (int kg = kg0; kg < kg0 + 16; kg++) {
                float x0 = xp[(size_t)(kg*4+0)*B_], x1 = xp[(size_t)(kg*4+1)*B_];
                float x2 = xp[(size_t)(kg*4+2)*B_], x3 = xp[(size_t)(kg*4+3)*B_];
                float h0 = hp[(size_t)(kg*4+0)*B_], h1 = hp[(size_t)(kg*4+1)*B_];
                float h2 = hp[(size_t)(kg*4+2)*B_], h3 = hp[(size_t)(kg*4+3)*B_];
                #pragma unroll
                for (int i = 0; i < 12; i++) {
                    float4 wi = sWi1[i*128 + kg];
                    float4 wh = sWh1[i*128 + kg];
                    acc[i]    = fmaf(wi.x,x0,fmaf(wi.y,x1,fmaf(wi.z,x2,fmaf(wi.w,x3,acc[i]))));
                    acc[12+i] = fmaf(wh.x,h0,fmaf(wh.y,h1,fmaf(wh.z,h2,fmaf(wh.w,h3,acc[12+i]))));
                }
            }
            #pragma unroll
            for (int i = 0; i < 24; i++) red[(wid*24 + i)*32 + lane] = acc[i];
            __syncthreads();
            for (int idx = tid; idx < 24*32; idx += NTHR) {
                int i = idx >> 5, b = idx & 31;
                float s = 0.0f;
                #pragma unroll
                for (int w = 0; w < 8; w++) s += red[(w*24 + i)*32 + b];
                fin[idx] = s;
            }
            __syncthreads();
            if (tid < 128) {
                int jr = tid >> 5, b = lane, j = j0 + jr;
                float gir = d1Bih[j]      + fin[(0*4+jr)*32 + b];
                float giz = d1Bih[H_+j]   + fin[(1*4+jr)*32 + b];
                float gin = d1Bih[2*H_+j] + fin[(2*4+jr)*32 + b];
                float ghr = d1Bhh[j]      + fin[(12+0*4+jr)*32 + b];
                float ghz = d1Bhh[H_+j]   + fin[(12+1*4+jr)*32 + b];
                float ghn = d1Bhh[2*H_+j] + fin[(12+2*4+jr)*32 + b];
                float r = sigf(gir + ghr);
                float z = sigf(giz + ghz);
                float n = tanhf(gin + r*ghn);
                float h1v = (1.0f - z)*n + z*h1in[(size_t)j*B_ + b];
                h1out[(size_t)j*B_ + b] = h1v;
                g_h1rm[(size_t)(t*B_ + b)*H_ + j] = h1v;
            }
        }
        gbar(mygen, par);
    }
}

// =============================================================================
// Kernel 4: zero the t=0 output slice
// =============================================================================
__global__ void k_zero(float* __restrict__ out) {
    int i = blockIdx.x * blockDim.x + threadIdx.x;
    if (i < B_*V_) {
        int b = i / V_, v = i - b*V_;
        out[(size_t)b*T_*V_ + v] = 0.0f;
    }
}

// =============================================================================
// Kernel 5: final projection  C[2016,32000] = h1_all @ fc_W^T + fc_b
// =============================================================================
__global__ void __launch_bounds__(256)
k_fc(const float* __restrict__ W, const float* __restrict__ bias,
     float* __restrict__ out)
{
    __shared__ float As[16][128];
    __shared__ float Bs[16][128];
    const int tid  = threadIdx.x;
    const int row0 = blockIdx.y * 128;
    const int col0 = blockIdx.x * 128;

    const int warp = tid >> 5, lane = tid & 31;
    const int m0 = (warp & 3) * 32 + (lane & 3) * 8;
    const int n0 = (warp >> 2) * 64 + (lane >> 2) * 8;

    float acc[8][8];
    #pragma unroll
    for (int i = 0; i < 8; i++)
        #pragma unroll
        for (int j = 0; j < 8; j++) acc[i][j] = 0.0f;

    const int lr = tid >> 2;           // 0..63
    const int lk = (tid & 3) * 4;      // 0,4,8,12

    for (int kk0 = 0; kk0 < H_; kk0 += 16) {
        #pragma unroll
        for (int h = 0; h < 2; h++) {
            int r = row0 + lr + h*64;
            float4 v = make_float4(0.f, 0.f, 0.f, 0.f);
            if (r < M_FC)
                v = *reinterpret_cast<const float4*>(g_h1rm + (size_t)r*H_ + kk0 + lk);
            As[lk+0][lr + h*64] = v.x;
            As[lk+1][lr + h*64] = v.y;
            As[lk+2][lr + h*64] = v.z;
            As[lk+3][lr + h*64] = v.w;
        }
        #pragma unroll
        for (int h = 0; h < 2; h++) {
            int c = col0 + lr + h*64;
            float4 v = *reinterpret_cast<const float4*>(W + (size_t)c*H_ + kk0 + lk);
            Bs[lk+0][lr + h*64] = v.x;
            Bs[lk+1][lr + h*64] = v.y;
            Bs[lk+2][lr + h*64] = v.z;
            Bs[lk+3][lr + h*64] = v.w;
        }
        __syncthreads();
        #pragma unroll
        for (int kk = 0; kk < 16; kk++) {
            float4 a0 = *reinterpret_cast<const float4*>(&As[kk][m0]);
            float4 a1 = *reinterpret_cast<const float4*>(&As[kk][m0+4]);
            float4 b0 = *reinterpret_cast<const float4*>(&Bs[kk][n0]);
            float4 b1 = *reinterpret_cast<const float4*>(&Bs[kk][n0+4]);
            float av[8] = {a0.x,a0.y,a0.z,a0.w,a1.x,a1.y,a1.z,a1.w};
            float bv[8] = {b0.x,b0.y,b0.z,b0.w,b1.x,b1.y,b1.z,b1.w};
            #pragma unroll
            for (int i = 0; i < 8; i++)
                #pragma unroll
                for (int j = 0; j < 8; j++)
                    acc[i][j] = fmaf(av[i], bv[j], acc[i][j]);
        }
        __syncthreads();
    }

    #pragma unroll
    for (int i = 0; i < 8; i++) {
        int r = row0 + m0 + i;
        if (r >= M_FC) continue;
        int b = r & 31, t = r >> 5;
        float* o = out + (size_t)b*T_*V_ + (size_t)(t+1)*V_ + col0 + n0;
        #pragma unroll
        for (int j = 0; j < 8; j += 4) {
            float4 bb = *reinterpret_cast<const float4*>(bias + col0 + n0 + j);
            float4 v = make_float4(acc[i][j+0] + bb.x, acc[i][j+1] + bb.y,
                                   acc[i][j+2] + bb.z, acc[i][j+3] + bb.w);
            *reinterpret_cast<float4*>(o + j) = v;
        }
    }
}

// =============================================================================
extern "C" void kernel_launch(void* const* d_in, const int* in_sizes, int n_in,
                              void* d_out, int out_size)
{
    const int*   src       = (const int*)  d_in[0];
    const int*   trg       = (const int*)  d_in[1];
    const float* src_embed = (const float*)d_in[2];
    const float* trg_embed = (const float*)d_in[3];
    const float* eWih  = (const float*)d_in[4];
    const float* eWhh  = (const float*)d_in[5];
    const float* eBih  = (const float*)d_in[6];
    const float* eBhh  = (const float*)d_in[7];
    const float* d0Wih = (const float*)d_in[8];
    const float* d0Whh = (const float*)d_in[9];
    const float* d0Bih = (const float*)d_in[10];
    const float* d0Bhh = (const float*)d_in[11];
    const float* d1Wih = (const float*)d_in[12];
    const float* d1Whh = (const float*)d_in[13];
    const float* d1Bih = (const float*)d_in[14];
    const float* d1Bhh = (const float*)d_in[15];
    const float* attnW = (const float*)d_in[16];
    const float* attnB = (const float*)d_in[17];
    const float* vW    = (const float*)d_in[18];
    // d_in[19] = v_b : constant shift, cancels in softmax
    const float* fcW   = (const float*)d_in[20];
    const float* fcB   = (const float*)d_in[21];
    float* out = (float*)d_out;

    const int decSmem = D_TOTAL * (int)sizeof(float);       // ~149 KB
    const int epSmem  = 64*128*(int)sizeof(float4);         // 128 KB
    cudaFuncSetAttribute(k_decoder, cudaFuncAttributeMaxDynamicSharedMemorySize, decSmem);
    cudaFuncSetAttribute(k_encproj, cudaFuncAttributeMaxDynamicSharedMemorySize, epSmem);

    k_encoder<<<NBLK, NTHR>>>(src, trg, src_embed, trg_embed,
                              eWih, eWhh, eBih, eBhh, d0Wih, d0Bih);
    k_encproj<<<NBLK, NTHR, epSmem>>>(attnW, attnB);
    k_decoder<<<NBLK, NTHR, decSmem>>>(attnW, vW, d0Wih, d0Whh, d0Bhh,
                                       d1Wih, d1Whh, d1Bih, d1Bhh);
    k_zero<<<(B_*V_ + 255)/256, 256>>>(out);
    k_fc<<<dim3(V_/128, (M_FC + 127)/128), 256>>>(fcW, fcB, out);
}